// round 8
// baseline (speedup 1.0000x reference)
#include <cuda_runtime.h>
#include <math.h>
#include <stdint.h>

// Problem constants
#define BATCH    2
#define T_SEQ    2048
#define D_MODEL  1024
#define N_HEADS  16
#define HEAD_DIM 64
#define M_TOTAL  (BATCH * T_SEQ)          // 4096 rows
#define QKV_LD   (3 * D_MODEL)            // 3072

// Scratch (allocation-free rule: __device__ globals)
__device__ float g_qkv   [M_TOTAL * QKV_LD];    // [4096, 3072] tf32-rounded (gemm<ROUND>)
__device__ float g_attn  [M_TOTAL * D_MODEL];   // [4096, 1024] tf32-rounded by flash
__device__ float g_xr    [M_TOTAL * D_MODEL];   // tf32-rounded x
__device__ float g_wqkv_r[D_MODEL * QKV_LD];    // tf32-rounded w_qkv
__device__ float g_wout_r[D_MODEL * D_MODEL];   // tf32-rounded w_out

__device__ __forceinline__ float to_tf32(float x) {
    float y;
    asm("cvt.rna.tf32.f32 %0, %1;" : "=f"(y) : "f"(x));
    return y;
}
__device__ __forceinline__ uint32_t smem_u32(const void* p) {
    uint32_t a;
    asm("{ .reg .u64 t; cvta.to.shared.u64 t, %1; cvt.u32.u64 %0, t; }" : "=r"(a) : "l"(p));
    return a;
}
__device__ __forceinline__ void cp16(uint32_t dst, const void* src) {
    asm volatile("cp.async.cg.shared.global [%0], [%1], 16;" :: "r"(dst), "l"(src) : "memory");
}
#define MMA_TF32(D, A, B) \
    asm volatile("mma.sync.aligned.m16n8k8.row.col.f32.tf32.tf32.f32 " \
                 "{%0,%1,%2,%3}, {%4,%5,%6,%7}, {%8,%9}, {%0,%1,%2,%3};" \
                 : "+f"((D)[0]), "+f"((D)[1]), "+f"((D)[2]), "+f"((D)[3]) \
                 : "r"((A)[0]), "r"((A)[1]), "r"((A)[2]), "r"((A)[3]), \
                   "r"((B)[0]), "r"((B)[1]))
#define LDMATRIX_X4(R, ADDR) \
    asm volatile("ldmatrix.sync.aligned.m8n8.x4.shared.b16 {%0,%1,%2,%3}, [%4];" \
                 : "=r"((R)[0]), "=r"((R)[1]), "=r"((R)[2]), "=r"((R)[3]) : "r"(ADDR))

// ---------------------------------------------------------------------------
// tf32 mma.sync GEMM (R5-R7, validated; optional tf32 rounding of output).
// ---------------------------------------------------------------------------
#define GS_A_FLOATS (128 * 36)
#define GS_B_FLOATS (32 * 136)
#define GS_STAGE    (GS_A_FLOATS + GS_B_FLOATS)   // 8960 floats
#define GS_SMEM_BYTES (3 * GS_STAGE * 4)          // 107520 B

__device__ __forceinline__ void issue_stage(uint32_t sb, const float* __restrict__ A,
                                            const float* __restrict__ B,
                                            int tid, int row0, int col0, int k0,
                                            int N, int K) {
#pragma unroll
    for (int i = 0; i < 4; i++) {
        int ff = tid + i * 256;
        int r  = ff >> 3, c4 = (ff & 7) * 4;
        cp16(sb + (r * 36 + c4) * 4, &A[(size_t)(row0 + r) * K + k0 + c4]);
        int k  = ff >> 5, n4 = (ff & 31) * 4;
        cp16(sb + (GS_A_FLOATS + k * 136 + n4) * 4, &B[(size_t)(k0 + k) * N + col0 + n4]);
    }
}

template <bool ROUND>
__global__ __launch_bounds__(256, 2) void gemm_mma(const float* __restrict__ A,
                                                   const float* __restrict__ B,
                                                   float* __restrict__ C,
                                                   int M, int N, int K) {
    extern __shared__ __align__(16) float gsm[];
    const uint32_t sb = smem_u32(gsm);
    const int tid  = threadIdx.x;
    const int lane = tid & 31;
    const int wid  = tid >> 5;
    const int wr = wid >> 2, wc = wid & 3;
    const int g  = lane >> 2, tig = lane & 3;
    const int row0 = blockIdx.y * 128;
    const int col0 = blockIdx.x * 128;

    float d[4][4][4] = {};
    const int T = K >> 5;

    issue_stage(sb + 0 * GS_STAGE * 4, A, B, tid, row0, col0, 0, N, K);
    asm volatile("cp.async.commit_group;" ::: "memory");
    issue_stage(sb + 1 * GS_STAGE * 4, A, B, tid, row0, col0, 32, N, K);
    asm volatile("cp.async.commit_group;" ::: "memory");

    const uint32_t a_base = sb + ((wr * 64 + ((lane >> 3) & 1) * 8 + (lane & 7)) * 36
                                  + ((lane >> 4) & 1) * 4) * 4;

    for (int t = 0; t < T; t++) {
        const int s = t % 3;
        asm volatile("cp.async.wait_group 1;" ::: "memory");
        __syncthreads();

        const uint32_t aS = a_base + s * GS_STAGE * 4;
        const uint32_t* sBu = (const uint32_t*)(gsm + s * GS_STAGE + GS_A_FLOATS);
        const int bcol = wc * 32 + g;

#pragma unroll
        for (int ks = 0; ks < 4; ks++) {
            uint32_t af[4][4], bf[4][2];
#pragma unroll
            for (int ma = 0; ma < 4; ma++)
                LDMATRIX_X4(af[ma], aS + ma * 2304 + ks * 32);
#pragma unroll
            for (int na = 0; na < 4; na++) {
                bf[na][0] = sBu[(ks * 8 + tig) * 136 + bcol + na * 8];
                bf[na][1] = sBu[(ks * 8 + tig + 4) * 136 + bcol + na * 8];
            }
#pragma unroll
            for (int ma = 0; ma < 4; ma++)
#pragma unroll
                for (int na = 0; na < 4; na++)
                    MMA_TF32(d[ma][na], af[ma], bf[na]);
        }

        if (t + 2 < T)
            issue_stage(sb + ((t + 2) % 3) * GS_STAGE * 4, A, B, tid,
                        row0, col0, (t + 2) * 32, N, K);
        asm volatile("cp.async.commit_group;" ::: "memory");
    }

#pragma unroll
    for (int ma = 0; ma < 4; ma++)
#pragma unroll
        for (int na = 0; na < 4; na++) {
            const int r = row0 + wr * 64 + ma * 16 + g;
            const int c = col0 + wc * 32 + na * 8 + tig * 2;
            float4 v = make_float4(d[ma][na][0], d[ma][na][1], d[ma][na][2], d[ma][na][3]);
            if (ROUND) {
                v.x = to_tf32(v.x); v.y = to_tf32(v.y);
                v.z = to_tf32(v.z); v.w = to_tf32(v.w);
            }
            *(float2*)&C[(size_t)r * N + c]       = make_float2(v.x, v.y);
            *(float2*)&C[(size_t)(r + 8) * N + c] = make_float2(v.z, v.w);
        }
}

// ---------------------------------------------------------------------------
// Elementwise tf32 pre-round
// ---------------------------------------------------------------------------
__global__ void round_tf32_kernel(const float* __restrict__ in, float* __restrict__ out,
                                  int n4) {
    int i = blockIdx.x * blockDim.x + threadIdx.x;
    if (i < n4) {
        float4 v = ((const float4*)in)[i];
        v.x = to_tf32(v.x); v.y = to_tf32(v.y);
        v.z = to_tf32(v.z); v.w = to_tf32(v.w);
        ((float4*)out)[i] = v;
    }
}

// ---------------------------------------------------------------------------
// Causal flash attention (tf32 mma.sync), R8 tiling:
//  8 warps = 4 wq (32 q rows each, 2 m-atoms) x 2 wk (32 keys each).
//  Each K/V B-fragment feeds 2 MMAs (2 m-atoms) -> fragment LDS traffic halved.
//  Softmax stats merged across the wk pair via smem (local-max rescale trick).
//  O accumulated per-warp over its 32 keys; pair-summed in the epilogue.
//  Q fragments hoisted to registers once; double-buffered KV cp.async stages.
// ---------------------------------------------------------------------------
#define FK_STRIDE 68
#define FV_STRIDE 72
#define FP_STRIDE 68
#define F_STAGE_FLOATS (64 * FK_STRIDE + 64 * FV_STRIDE)   // 8960
#define F_PS (2 * F_STAGE_FLOATS)                          // 17920
#define F_ST (F_PS + 128 * FP_STRIDE)                      // stats: float2[2][128]
#define F_SMEM_FLOATS (F_ST + 512)                         // 27136 fl = 108544 B

__global__ __launch_bounds__(256, 1) void flash_mma_kernel() {
    extern __shared__ __align__(16) float fsm[];
    const uint32_t sb = smem_u32(fsm);
    const int tid  = threadIdx.x;
    const int lane = tid & 31;
    const int wid  = tid >> 5;
    const int wq   = wid >> 1;        // 0..3 : q rows [32wq, 32wq+32)
    const int wk   = wid & 1;         // 0..1 : keys  [32wk, 32wk+32) of tile
    const int g    = lane >> 2;
    const int tig  = lane & 3;
    const float NEG_INF = __int_as_float(0xff800000u);

    const int qt = (gridDim.x - 1) - blockIdx.x;     // reversed: heavy first
    const int bh = blockIdx.y;
    const int b  = bh >> 4;
    const int h  = bh & 15;
    const int q0 = qt * 128;

    const float* base = g_qkv + (size_t)b * T_SEQ * QKV_LD + h * HEAD_DIM;
    const float* Qg = base;
    const float* Kg = base + D_MODEL;
    const float* Vg = base + 2 * D_MODEL;

    // ---- prologue: Q -> stage-0 region; KV(0) -> stage 1 ----
#pragma unroll
    for (int i = 0; i < 8; i++) {
        int ff = tid + i * 256;
        int r  = ff >> 4;
        int d4 = (ff & 15) * 4;
        cp16(sb + (r * FK_STRIDE + d4) * 4, &Qg[(size_t)(q0 + r) * QKV_LD + d4]);
    }
    asm volatile("cp.async.commit_group;" ::: "memory");
#pragma unroll
    for (int i = 0; i < 4; i++) {
        int ff = tid + i * 256;
        int r  = ff >> 4;
        int d4 = (ff & 15) * 4;
        const size_t grow = (size_t)r * QKV_LD + d4;
        cp16(sb + (F_STAGE_FLOATS + r * FK_STRIDE + d4) * 4, &Kg[grow]);
        cp16(sb + (F_STAGE_FLOATS + 64 * FK_STRIDE + r * FV_STRIDE + d4) * 4, &Vg[grow]);
    }
    asm volatile("cp.async.commit_group;" ::: "memory");
    asm volatile("cp.async.wait_group 1;" ::: "memory");   // Q complete
    __syncthreads();

    // ---- Q fragments (2 m-atoms x 8 ks), hoisted once ----
    const int lm_rr  = ((lane >> 3) & 1) * 8 + (lane & 7);
    const int lm_col = ((lane >> 4) & 1) * 4;
    uint32_t qf[2][8][4];
#pragma unroll
    for (int ma = 0; ma < 2; ma++)
#pragma unroll
        for (int ks = 0; ks < 8; ks++)
            LDMATRIX_X4(qf[ma][ks],
                        sb + ((wq * 32 + ma * 16 + lm_rr) * FK_STRIDE + lm_col + ks * 8) * 4);
    __syncthreads();              // Q region (stage 0) now free for KV(1)

    const uint32_t p_lm0 = sb + (F_PS + (wq * 32 + lm_rr) * FP_STRIDE + wk * 32 + lm_col) * 4;
    const uint32_t p_lm1 = p_lm0 + 16 * FP_STRIDE * 4;

    float o[2][8][4] = {};
    float m_[2][2], l_[2][2];
#pragma unroll
    for (int ma = 0; ma < 2; ma++)
        for (int hh = 0; hh < 2; hh++) { m_[ma][hh] = NEG_INF; l_[ma][hh] = 0.f; }

    const float scale = 0.125f;
    const int nkt = 2 * qt + 2;
    for (int kt = 0; kt < nkt; kt++) {
        const int s = (kt + 1) & 1;          // stage holding KV(kt)
        if (kt + 1 < nkt) {
            const int sd = kt & 1;
#pragma unroll
            for (int i = 0; i < 4; i++) {
                int ff = tid + i * 256;
                int r  = ff >> 4;
                int d4 = (ff & 15) * 4;
                const size_t grow = (size_t)((kt + 1) * 64 + r) * QKV_LD + d4;
                cp16(sb + (sd * F_STAGE_FLOATS + r * FK_STRIDE + d4) * 4, &Kg[grow]);
                cp16(sb + (sd * F_STAGE_FLOATS + 64 * FK_STRIDE + r * FV_STRIDE + d4) * 4,
                     &Vg[grow]);
            }
            asm volatile("cp.async.commit_group;" ::: "memory");
            asm volatile("cp.async.wait_group 1;" ::: "memory");
        } else {
            asm volatile("cp.async.wait_group 0;" ::: "memory");
        }
        __syncthreads();

        const float* Ks = fsm + s * F_STAGE_FLOATS;
        const float* Vs = Ks + 64 * FK_STRIDE;

        // ---- S = Q K^T : 8 ks x 4 na, each B fragment feeds 2 m-atoms ----
        float sf[2][4][4] = {};
#pragma unroll
        for (int ks = 0; ks < 8; ks++) {
#pragma unroll
            for (int na = 0; na < 4; na++) {
                uint32_t bf[2];
                bf[0] = __float_as_uint(Ks[(wk * 32 + na * 8 + g) * FK_STRIDE + ks * 8 + tig]);
                bf[1] = __float_as_uint(Ks[(wk * 32 + na * 8 + g) * FK_STRIDE + ks * 8 + tig + 4]);
                MMA_TF32(sf[0][na], qf[0][ks], bf);
                MMA_TF32(sf[1][na], qf[1][ks], bf);
            }
        }

        // ---- scale + causal mask ----
        const bool diag = (kt >= 2 * qt);
#pragma unroll
        for (int ma = 0; ma < 2; ma++) {
            const int qr0 = q0 + wq * 32 + ma * 16 + g;
            const int qr1 = qr0 + 8;
#pragma unroll
            for (int na = 0; na < 4; na++) {
                const int kg = kt * 64 + wk * 32 + na * 8 + 2 * tig;
                sf[ma][na][0] *= scale; sf[ma][na][1] *= scale;
                sf[ma][na][2] *= scale; sf[ma][na][3] *= scale;
                if (diag) {
                    if (kg     > qr0) sf[ma][na][0] = NEG_INF;
                    if (kg + 1 > qr0) sf[ma][na][1] = NEG_INF;
                    if (kg     > qr1) sf[ma][na][2] = NEG_INF;
                    if (kg + 1 > qr1) sf[ma][na][3] = NEG_INF;
                }
            }
        }

        // ---- per-warp local max + local exp-sum (quad-reduced) ----
        float mx[2][2], sm[2][2];
#pragma unroll
        for (int ma = 0; ma < 2; ma++) {
            float v0 = NEG_INF, v1 = NEG_INF;
#pragma unroll
            for (int na = 0; na < 4; na++) {
                v0 = fmaxf(v0, fmaxf(sf[ma][na][0], sf[ma][na][1]));
                v1 = fmaxf(v1, fmaxf(sf[ma][na][2], sf[ma][na][3]));
            }
            v0 = fmaxf(v0, __shfl_xor_sync(0xffffffffu, v0, 1));
            v0 = fmaxf(v0, __shfl_xor_sync(0xffffffffu, v0, 2));
            v1 = fmaxf(v1, __shfl_xor_sync(0xffffffffu, v1, 1));
            v1 = fmaxf(v1, __shfl_xor_sync(0xffffffffu, v1, 2));
            mx[ma][0] = fmaxf(v0, -1e30f);     // clamp: all-masked warp stays finite
            mx[ma][1] = fmaxf(v1, -1e30f);
            float s0 = 0.f, s1 = 0.f;
#pragma unroll
            for (int na = 0; na < 4; na++) {
                sf[ma][na][0] = __expf(sf[ma][na][0] - mx[ma][0]);
                sf[ma][na][1] = __expf(sf[ma][na][1] - mx[ma][0]);
                sf[ma][na][2] = __expf(sf[ma][na][2] - mx[ma][1]);
                sf[ma][na][3] = __expf(sf[ma][na][3] - mx[ma][1]);
                s0 += sf[ma][na][0] + sf[ma][na][1];
                s1 += sf[ma][na][2] + sf[ma][na][3];
            }
            s0 += __shfl_xor_sync(0xffffffffu, s0, 1);
            s0 += __shfl_xor_sync(0xffffffffu, s0, 2);
            s1 += __shfl_xor_sync(0xffffffffu, s1, 1);
            s1 += __shfl_xor_sync(0xffffffffu, s1, 2);
            sm[ma][0] = s0; sm[ma][1] = s1;
        }

        // ---- exchange (max, sum) across the wk pair ----
        if (tig == 0) {
#pragma unroll
            for (int ma = 0; ma < 2; ma++)
#pragma unroll
                for (int hh = 0; hh < 2; hh++) {
                    const int row = wq * 32 + ma * 16 + hh * 8 + g;
                    *(float2*)&fsm[F_ST + (wk * 128 + row) * 2] =
                        make_float2(mx[ma][hh], sm[ma][hh]);
                }
        }
        __syncthreads();

        float cc[2][2], al[2][2];
#pragma unroll
        for (int ma = 0; ma < 2; ma++)
#pragma unroll
            for (int hh = 0; hh < 2; hh++) {
                const int row = wq * 32 + ma * 16 + hh * 8 + g;
                const float2 s0 = *(const float2*)&fsm[F_ST + row * 2];
                const float2 s1 = *(const float2*)&fsm[F_ST + (128 + row) * 2];
                const float mn = fmaxf(m_[ma][hh], fmaxf(s0.x, s1.x));
                const float alpha = __expf(m_[ma][hh] - mn);
                l_[ma][hh] = l_[ma][hh] * alpha
                           + __expf(s0.x - mn) * s0.y + __expf(s1.x - mn) * s1.y;
                m_[ma][hh] = mn;
                cc[ma][hh] = __expf(mx[ma][hh] - mn);
                al[ma][hh] = alpha;
            }
#pragma unroll
        for (int ma = 0; ma < 2; ma++)
#pragma unroll
            for (int na = 0; na < 8; na++) {
                o[ma][na][0] *= al[ma][0]; o[ma][na][1] *= al[ma][0];
                o[ma][na][2] *= al[ma][1]; o[ma][na][3] *= al[ma][1];
            }

        // ---- P (rescaled to global max, tf32) -> warp-private smem quadrant ----
#pragma unroll
        for (int ma = 0; ma < 2; ma++) {
            const int pr0 = wq * 32 + ma * 16 + g;
            const int kc  = wk * 32 + 2 * tig;
#pragma unroll
            for (int na = 0; na < 4; na++) {
                *(float2*)&fsm[F_PS + pr0 * FP_STRIDE + na * 8 + kc] =
                    make_float2(to_tf32(sf[ma][na][0] * cc[ma][0]),
                                to_tf32(sf[ma][na][1] * cc[ma][0]));
                *(float2*)&fsm[F_PS + (pr0 + 8) * FP_STRIDE + na * 8 + kc] =
                    make_float2(to_tf32(sf[ma][na][2] * cc[ma][1]),
                                to_tf32(sf[ma][na][3] * cc[ma][1]));
            }
        }
        __syncwarp();

        // ---- O += P V over this warp's 32 keys : 4 k2 x 8 na(d) ----
#pragma unroll
        for (int k2 = 0; k2 < 4; k2++) {
            uint32_t pf0[4], pf1[4];
            LDMATRIX_X4(pf0, p_lm0 + k2 * 32);
            LDMATRIX_X4(pf1, p_lm1 + k2 * 32);
#pragma unroll
            for (int na = 0; na < 8; na++) {
                uint32_t bf[2];
                bf[0] = __float_as_uint(Vs[(wk * 32 + k2 * 8 + tig) * FV_STRIDE + na * 8 + g]);
                bf[1] = __float_as_uint(Vs[(wk * 32 + k2 * 8 + tig + 4) * FV_STRIDE + na * 8 + g]);
                MMA_TF32(o[0][na], pf0, bf);
                MMA_TF32(o[1][na], pf1, bf);
            }
        }
        __syncthreads();          // all warps done with stage s -> reusable
    }

    // ---- epilogue: pair-sum O across wk, /l, tf32-round, store ----
    if (wk == 1) {
#pragma unroll
        for (int ma = 0; ma < 2; ma++) {
            const int pr0 = wq * 32 + ma * 16 + g;
#pragma unroll
            for (int na = 0; na < 8; na++) {
                *(float2*)&fsm[F_PS + pr0 * FP_STRIDE + na * 8 + 2 * tig] =
                    make_float2(o[ma][na][0], o[ma][na][1]);
                *(float2*)&fsm[F_PS + (pr0 + 8) * FP_STRIDE + na * 8 + 2 * tig] =
                    make_float2(o[ma][na][2], o[ma][na][3]);
            }
        }
    }
    __syncthreads();
    if (wk == 0) {
#pragma unroll
        for (int ma = 0; ma < 2; ma++) {
            const float i0 = 1.f / l_[ma][0];
            const float i1 = 1.f / l_[ma][1];
            const int pr0 = wq * 32 + ma * 16 + g;
            const int r0 = q0 + pr0;
            float* out0 = &g_attn[(size_t)(b * T_SEQ + r0) * D_MODEL + h * HEAD_DIM + 2 * tig];
            float* out1 = &g_attn[(size_t)(b * T_SEQ + r0 + 8) * D_MODEL + h * HEAD_DIM + 2 * tig];
#pragma unroll
            for (int na = 0; na < 8; na++) {
                const float2 p0 = *(const float2*)&fsm[F_PS + pr0 * FP_STRIDE + na * 8 + 2 * tig];
                const float2 p1 = *(const float2*)&fsm[F_PS + (pr0 + 8) * FP_STRIDE + na * 8 + 2 * tig];
                *(float2*)&out0[na * 8] = make_float2(to_tf32((o[ma][na][0] + p0.x) * i0),
                                                      to_tf32((o[ma][na][1] + p0.y) * i0));
                *(float2*)&out1[na * 8] = make_float2(to_tf32((o[ma][na][2] + p1.x) * i1),
                                                      to_tf32((o[ma][na][3] + p1.y) * i1));
            }
        }
    }
}

// ---------------------------------------------------------------------------
// Launch
// ---------------------------------------------------------------------------
extern "C" void kernel_launch(void* const* d_in, const int* in_sizes, int n_in,
                              void* d_out, int out_size) {
    const float* x     = (const float*)d_in[0];   // [2,2048,1024]
    const float* w_qkv = (const float*)d_in[1];   // [1024,3072]
    const float* w_out = (const float*)d_in[2];   // [1024,1024]
    float* out = (float*)d_out;                   // [2,2048,1024]

    void *qkv_p, *attn_p, *xr_p, *wqkv_p, *wout_p;
    cudaGetSymbolAddress(&qkv_p,  g_qkv);
    cudaGetSymbolAddress(&attn_p, g_attn);
    cudaGetSymbolAddress(&xr_p,   g_xr);
    cudaGetSymbolAddress(&wqkv_p, g_wqkv_r);
    cudaGetSymbolAddress(&wout_p, g_wout_r);

    const int fa_smem = F_SMEM_FLOATS * (int)sizeof(float);    // 108544 B
    cudaFuncSetAttribute(flash_mma_kernel,
                         cudaFuncAttributeMaxDynamicSharedMemorySize, fa_smem);
    cudaFuncSetAttribute(gemm_mma<true>,
                         cudaFuncAttributeMaxDynamicSharedMemorySize, GS_SMEM_BYTES);
    cudaFuncSetAttribute(gemm_mma<false>,
                         cudaFuncAttributeMaxDynamicSharedMemorySize, GS_SMEM_BYTES);

    // 0) pre-round inputs to tf32
    {
        int n4 = M_TOTAL * D_MODEL / 4;
        round_tf32_kernel<<<(n4 + 255) / 256, 256>>>(x, (float*)xr_p, n4);
        n4 = D_MODEL * QKV_LD / 4;
        round_tf32_kernel<<<(n4 + 255) / 256, 256>>>(w_qkv, (float*)wqkv_p, n4);
        n4 = D_MODEL * D_MODEL / 4;
        round_tf32_kernel<<<(n4 + 255) / 256, 256>>>(w_out, (float*)wout_p, n4);
    }

    // 1) QKV projection (output tf32-rounded)
    gemm_mma<true><<<dim3(QKV_LD / 128, M_TOTAL / 128), 256, GS_SMEM_BYTES>>>(
        (const float*)xr_p, (const float*)wqkv_p, (float*)qkv_p,
        M_TOTAL, QKV_LD, D_MODEL);

    // 2) causal flash attention (tensor cores, amortized B fragments)
    flash_mma_kernel<<<dim3(T_SEQ / 128, BATCH * N_HEADS), 256, fa_smem>>>();

    // 3) output projection
    gemm_mma<false><<<dim3(D_MODEL / 128, M_TOTAL / 128), 256, GS_SMEM_BYTES>>>(
        (const float*)attn_p, (const float*)wout_p, out,
        M_TOTAL, D_MODEL, D_MODEL);
}

// round 9
// speedup vs baseline: 1.0145x; 1.0145x over previous
#include <cuda_runtime.h>
#include <math.h>
#include <stdint.h>

// Problem constants
#define BATCH    2
#define T_SEQ    2048
#define D_MODEL  1024
#define N_HEADS  16
#define HEAD_DIM 64
#define M_TOTAL  (BATCH * T_SEQ)          // 4096 rows
#define QKV_LD   (3 * D_MODEL)            // 3072

// Scratch (allocation-free rule: __device__ globals)
__device__ float g_qkv   [M_TOTAL * QKV_LD];    // [4096, 3072] tf32-rounded (gemm<ROUND>)
__device__ float g_attn  [M_TOTAL * D_MODEL];   // [4096, 1024] tf32-rounded by flash
__device__ float g_xr    [M_TOTAL * D_MODEL];   // tf32-rounded x
__device__ float g_wqkv_r[D_MODEL * QKV_LD];    // tf32-rounded w_qkv
__device__ float g_wout_r[D_MODEL * D_MODEL];   // tf32-rounded w_out

__device__ __forceinline__ float to_tf32(float x) {
    float y;
    asm("cvt.rna.tf32.f32 %0, %1;" : "=f"(y) : "f"(x));
    return y;
}
__device__ __forceinline__ uint32_t smem_u32(const void* p) {
    uint32_t a;
    asm("{ .reg .u64 t; cvta.to.shared.u64 t, %1; cvt.u32.u64 %0, t; }" : "=r"(a) : "l"(p));
    return a;
}
__device__ __forceinline__ void cp16(uint32_t dst, const void* src) {
    asm volatile("cp.async.cg.shared.global [%0], [%1], 16;" :: "r"(dst), "l"(src) : "memory");
}
#define MMA_TF32(D, A, B) \
    asm volatile("mma.sync.aligned.m16n8k8.row.col.f32.tf32.tf32.f32 " \
                 "{%0,%1,%2,%3}, {%4,%5,%6,%7}, {%8,%9}, {%0,%1,%2,%3};" \
                 : "+f"((D)[0]), "+f"((D)[1]), "+f"((D)[2]), "+f"((D)[3]) \
                 : "r"((A)[0]), "r"((A)[1]), "r"((A)[2]), "r"((A)[3]), \
                   "r"((B)[0]), "r"((B)[1]))
#define LDMATRIX_X4(R, ADDR) \
    asm volatile("ldmatrix.sync.aligned.m8n8.x4.shared.b16 {%0,%1,%2,%3}, [%4];" \
                 : "=r"((R)[0]), "=r"((R)[1]), "=r"((R)[2]), "=r"((R)[3]) : "r"(ADDR))

// ---------------------------------------------------------------------------
// tf32 mma.sync GEMM. R9: manual software pipeline of fragments across ks —
// double-buffered af/bf so ks+1 fragment loads overlap ks's 16 MMAs.
// 128x128 block tile, 8 warps (2x4), warp tile 64x32, K-tile 32, 3-stage
// cp.async. A smem [128][36] (ldmatrix conflict-free), B [32][136] natural.
// ---------------------------------------------------------------------------
#define GS_A_FLOATS (128 * 36)
#define GS_B_FLOATS (32 * 136)
#define GS_STAGE    (GS_A_FLOATS + GS_B_FLOATS)   // 8960 floats
#define GS_SMEM_BYTES (3 * GS_STAGE * 4)          // 107520 B

__device__ __forceinline__ void issue_stage(uint32_t sb, const float* __restrict__ A,
                                            const float* __restrict__ B,
                                            int tid, int row0, int col0, int k0,
                                            int N, int K) {
#pragma unroll
    for (int i = 0; i < 4; i++) {
        int ff = tid + i * 256;
        int r  = ff >> 3, c4 = (ff & 7) * 4;
        cp16(sb + (r * 36 + c4) * 4, &A[(size_t)(row0 + r) * K + k0 + c4]);
        int k  = ff >> 5, n4 = (ff & 31) * 4;
        cp16(sb + (GS_A_FLOATS + k * 136 + n4) * 4, &B[(size_t)(k0 + k) * N + col0 + n4]);
    }
}

template <bool ROUND>
__global__ __launch_bounds__(256, 2) void gemm_mma(const float* __restrict__ A,
                                                   const float* __restrict__ B,
                                                   float* __restrict__ C,
                                                   int M, int N, int K) {
    extern __shared__ __align__(16) float gsm[];
    const uint32_t sb = smem_u32(gsm);
    const int tid  = threadIdx.x;
    const int lane = tid & 31;
    const int wid  = tid >> 5;
    const int wr = wid >> 2, wc = wid & 3;
    const int g  = lane >> 2, tig = lane & 3;
    const int row0 = blockIdx.y * 128;
    const int col0 = blockIdx.x * 128;

    float d[4][4][4] = {};
    const int T = K >> 5;

    issue_stage(sb + 0 * GS_STAGE * 4, A, B, tid, row0, col0, 0, N, K);
    asm volatile("cp.async.commit_group;" ::: "memory");
    issue_stage(sb + 1 * GS_STAGE * 4, A, B, tid, row0, col0, 32, N, K);
    asm volatile("cp.async.commit_group;" ::: "memory");

    const uint32_t a_base = sb + ((wr * 64 + ((lane >> 3) & 1) * 8 + (lane & 7)) * 36
                                  + ((lane >> 4) & 1) * 4) * 4;

    for (int t = 0; t < T; t++) {
        const int s = t % 3;
        asm volatile("cp.async.wait_group 1;" ::: "memory");
        __syncthreads();

        const uint32_t aS = a_base + s * GS_STAGE * 4;
        const uint32_t* sBu = (const uint32_t*)(gsm + s * GS_STAGE + GS_A_FLOATS);
        const int bcol = wc * 32 + g;

        // ---- software-pipelined fragment loads across ks ----
        uint32_t af[2][4][4], bf[2][4][2];
#pragma unroll
        for (int ma = 0; ma < 4; ma++)
            LDMATRIX_X4(af[0][ma], aS + ma * 2304);
#pragma unroll
        for (int na = 0; na < 4; na++) {
            bf[0][na][0] = sBu[tig * 136 + bcol + na * 8];
            bf[0][na][1] = sBu[(tig + 4) * 136 + bcol + na * 8];
        }
#pragma unroll
        for (int ks = 0; ks < 4; ks++) {
            const int cur = ks & 1, nxt = cur ^ 1;
            if (ks < 3) {
#pragma unroll
                for (int ma = 0; ma < 4; ma++)
                    LDMATRIX_X4(af[nxt][ma], aS + ma * 2304 + (ks + 1) * 32);
#pragma unroll
                for (int na = 0; na < 4; na++) {
                    bf[nxt][na][0] = sBu[((ks + 1) * 8 + tig) * 136 + bcol + na * 8];
                    bf[nxt][na][1] = sBu[((ks + 1) * 8 + tig + 4) * 136 + bcol + na * 8];
                }
            }
#pragma unroll
            for (int ma = 0; ma < 4; ma++)
#pragma unroll
                for (int na = 0; na < 4; na++)
                    MMA_TF32(d[ma][na], af[cur][ma], bf[cur][na]);
        }

        if (t + 2 < T)
            issue_stage(sb + ((t + 2) % 3) * GS_STAGE * 4, A, B, tid,
                        row0, col0, (t + 2) * 32, N, K);
        asm volatile("cp.async.commit_group;" ::: "memory");
    }

#pragma unroll
    for (int ma = 0; ma < 4; ma++)
#pragma unroll
        for (int na = 0; na < 4; na++) {
            const int r = row0 + wr * 64 + ma * 16 + g;
            const int c = col0 + wc * 32 + na * 8 + tig * 2;
            float4 v = make_float4(d[ma][na][0], d[ma][na][1], d[ma][na][2], d[ma][na][3]);
            if (ROUND) {
                v.x = to_tf32(v.x); v.y = to_tf32(v.y);
                v.z = to_tf32(v.z); v.w = to_tf32(v.w);
            }
            *(float2*)&C[(size_t)r * N + c]       = make_float2(v.x, v.y);
            *(float2*)&C[(size_t)(r + 8) * N + c] = make_float2(v.z, v.w);
        }
}

// ---------------------------------------------------------------------------
// Fused tf32 pre-round: one kernel covers x, w_qkv, w_out
// ---------------------------------------------------------------------------
#define RN_X  (M_TOTAL * D_MODEL / 4)       // 1048576 float4
#define RN_WQ (D_MODEL * QKV_LD / 4)        //  786432
#define RN_WO (D_MODEL * D_MODEL / 4)       //  262144
#define RN_TOTAL (RN_X + RN_WQ + RN_WO)     // 2097152

__global__ void round_all_kernel(const float* __restrict__ x,
                                 const float* __restrict__ wq,
                                 const float* __restrict__ wo) {
    int i = blockIdx.x * blockDim.x + threadIdx.x;
    if (i >= RN_TOTAL) return;
    const float4* src;
    float4* dst;
    if (i < RN_X) {
        src = (const float4*)x + i;          dst = (float4*)g_xr + i;
    } else if (i < RN_X + RN_WQ) {
        src = (const float4*)wq + (i - RN_X); dst = (float4*)g_wqkv_r + (i - RN_X);
    } else {
        src = (const float4*)wo + (i - RN_X - RN_WQ);
        dst = (float4*)g_wout_r + (i - RN_X - RN_WQ);
    }
    float4 v = *src;
    v.x = to_tf32(v.x); v.y = to_tf32(v.y);
    v.z = to_tf32(v.z); v.w = to_tf32(v.w);
    *dst = v;
}

// ---------------------------------------------------------------------------
// Causal flash attention (tf32 mma.sync) — exact R7 config (best known):
//  Q fragments hoisted once, double-buffered KV cp.async, warp-private P,
//  8 warps each owning 16 q rows, 2 blocks/SM.
// ---------------------------------------------------------------------------
#define FK_STRIDE 68
#define FV_STRIDE 72
#define FP_STRIDE 68
#define F_STAGE_FLOATS (64 * FK_STRIDE + 64 * FV_STRIDE)   // 8960
#define F_PS (2 * F_STAGE_FLOATS)                          // 17920
#define F_SMEM_FLOATS (F_PS + 128 * FP_STRIDE)             // 26624 fl = 106496 B

__global__ __launch_bounds__(256, 2) void flash_mma_kernel() {
    extern __shared__ __align__(16) float fsm[];
    const uint32_t sb = smem_u32(fsm);
    const int tid  = threadIdx.x;
    const int lane = tid & 31;
    const int wid  = tid >> 5;
    const int g    = lane >> 2;
    const int tig  = lane & 3;

    const int qt = (gridDim.x - 1) - blockIdx.x;     // reversed: heavy first
    const int bh = blockIdx.y;
    const int b  = bh >> 4;
    const int h  = bh & 15;
    const int q0 = qt * 128;

    const float* base = g_qkv + (size_t)b * T_SEQ * QKV_LD + h * HEAD_DIM;
    const float* Qg = base;
    const float* Kg = base + D_MODEL;
    const float* Vg = base + 2 * D_MODEL;

    // ---- prologue: Q -> stage-0 region; KV(0) -> stage 1 ----
#pragma unroll
    for (int i = 0; i < 8; i++) {
        int ff = tid + i * 256;
        int r  = ff >> 4;
        int d4 = (ff & 15) * 4;
        cp16(sb + (r * FK_STRIDE + d4) * 4, &Qg[(size_t)(q0 + r) * QKV_LD + d4]);
    }
    asm volatile("cp.async.commit_group;" ::: "memory");
#pragma unroll
    for (int i = 0; i < 4; i++) {
        int ff = tid + i * 256;
        int r  = ff >> 4;
        int d4 = (ff & 15) * 4;
        const size_t grow = (size_t)r * QKV_LD + d4;
        cp16(sb + (F_STAGE_FLOATS + r * FK_STRIDE + d4) * 4, &Kg[grow]);
        cp16(sb + (F_STAGE_FLOATS + 64 * FK_STRIDE + r * FV_STRIDE + d4) * 4, &Vg[grow]);
    }
    asm volatile("cp.async.commit_group;" ::: "memory");
    asm volatile("cp.async.wait_group 1;" ::: "memory");   // Q complete
    __syncthreads();

    // ---- extract Q fragments once (loop-invariant) ----
    const int lm_row = wid * 16 + ((lane >> 3) & 1) * 8 + (lane & 7);
    const int lm_col = ((lane >> 4) & 1) * 4;
    uint32_t qf[8][4];
    {
        const uint32_t q_lm = sb + (lm_row * FK_STRIDE + lm_col) * 4;
#pragma unroll
        for (int ks = 0; ks < 8; ks++)
            LDMATRIX_X4(qf[ks], q_lm + ks * 32);
    }
    __syncthreads();              // Q region (stage 0) now free for KV(1)

    const uint32_t p_lm = sb + (F_PS + lm_row * FP_STRIDE + lm_col) * 4;

    const float NEG_INF = __int_as_float(0xff800000u);
    const float scale = 0.125f;
    float o[8][4] = {};
    float m0 = NEG_INF, m1 = NEG_INF, l0 = 0.f, l1 = 0.f;

    const int nkt = 2 * qt + 2;
    for (int kt = 0; kt < nkt; kt++) {
        const int s = (kt + 1) & 1;          // stage holding KV(kt)

        if (kt + 1 < nkt) {
            const int sd = kt & 1;
#pragma unroll
            for (int i = 0; i < 4; i++) {
                int ff = tid + i * 256;
                int r  = ff >> 4;
                int d4 = (ff & 15) * 4;
                const size_t grow = (size_t)((kt + 1) * 64 + r) * QKV_LD + d4;
                cp16(sb + (sd * F_STAGE_FLOATS + r * FK_STRIDE + d4) * 4, &Kg[grow]);
                cp16(sb + (sd * F_STAGE_FLOATS + 64 * FK_STRIDE + r * FV_STRIDE + d4) * 4,
                     &Vg[grow]);
            }
            asm volatile("cp.async.commit_group;" ::: "memory");
            asm volatile("cp.async.wait_group 1;" ::: "memory");   // KV(kt) ready
        } else {
            asm volatile("cp.async.wait_group 0;" ::: "memory");
        }
        __syncthreads();                      // KV(kt) visible to all warps

        const float* Ks = fsm + s * F_STAGE_FLOATS;
        const float* Vs = Ks + 64 * FK_STRIDE;

        // ---- S = Q K^T : 8 ks x 8 na ----
        float sfrag[8][4] = {};
#pragma unroll
        for (int ks = 0; ks < 8; ks++) {
#pragma unroll
            for (int na = 0; na < 8; na++) {
                uint32_t bf[2];
                bf[0] = __float_as_uint(Ks[(na * 8 + g) * FK_STRIDE + ks * 8 + tig]);
                bf[1] = __float_as_uint(Ks[(na * 8 + g) * FK_STRIDE + ks * 8 + tig + 4]);
                MMA_TF32(sfrag[na], qf[ks], bf);
            }
        }

        // ---- scale + causal mask ----
        const bool diag = (kt >= 2 * qt);
        const int qr0 = q0 + wid * 16 + g;
        const int qr1 = qr0 + 8;
#pragma unroll
        for (int na = 0; na < 8; na++) {
            const int kg = kt * 64 + na * 8 + 2 * tig;
            sfrag[na][0] *= scale; sfrag[na][1] *= scale;
            sfrag[na][2] *= scale; sfrag[na][3] *= scale;
            if (diag) {
                if (kg     > qr0) sfrag[na][0] = NEG_INF;
                if (kg + 1 > qr0) sfrag[na][1] = NEG_INF;
                if (kg     > qr1) sfrag[na][2] = NEG_INF;
                if (kg + 1 > qr1) sfrag[na][3] = NEG_INF;
            }
        }

        // ---- online softmax (rows g / g+8; reduce across quad tig) ----
        float mx0 = NEG_INF, mx1 = NEG_INF;
#pragma unroll
        for (int na = 0; na < 8; na++) {
            mx0 = fmaxf(mx0, fmaxf(sfrag[na][0], sfrag[na][1]));
            mx1 = fmaxf(mx1, fmaxf(sfrag[na][2], sfrag[na][3]));
        }
        mx0 = fmaxf(mx0, __shfl_xor_sync(0xffffffffu, mx0, 1));
        mx0 = fmaxf(mx0, __shfl_xor_sync(0xffffffffu, mx0, 2));
        mx1 = fmaxf(mx1, __shfl_xor_sync(0xffffffffu, mx1, 1));
        mx1 = fmaxf(mx1, __shfl_xor_sync(0xffffffffu, mx1, 2));
        const float mn0 = fmaxf(m0, mx0);
        const float mn1 = fmaxf(m1, mx1);
        const float a0 = __expf(m0 - mn0);
        const float a1 = __expf(m1 - mn1);
        float sum0 = 0.f, sum1 = 0.f;
#pragma unroll
        for (int na = 0; na < 8; na++) {
            sfrag[na][0] = __expf(sfrag[na][0] - mn0);
            sfrag[na][1] = __expf(sfrag[na][1] - mn0);
            sfrag[na][2] = __expf(sfrag[na][2] - mn1);
            sfrag[na][3] = __expf(sfrag[na][3] - mn1);
            sum0 += sfrag[na][0] + sfrag[na][1];
            sum1 += sfrag[na][2] + sfrag[na][3];
        }
        sum0 += __shfl_xor_sync(0xffffffffu, sum0, 1);
        sum0 += __shfl_xor_sync(0xffffffffu, sum0, 2);
        sum1 += __shfl_xor_sync(0xffffffffu, sum1, 1);
        sum1 += __shfl_xor_sync(0xffffffffu, sum1, 2);
        l0 = l0 * a0 + sum0;  m0 = mn0;
        l1 = l1 * a1 + sum1;  m1 = mn1;
#pragma unroll
        for (int na = 0; na < 8; na++) {
            o[na][0] *= a0; o[na][1] *= a0;
            o[na][2] *= a1; o[na][3] *= a1;
        }

        // ---- P (tf32) -> warp-private smem rows; __syncwarp suffices ----
        {
            const int pr0 = wid * 16 + g;
            const int kc  = 2 * tig;
#pragma unroll
            for (int na = 0; na < 8; na++) {
                *(float2*)&fsm[F_PS + pr0 * FP_STRIDE + na * 8 + kc] =
                    make_float2(to_tf32(sfrag[na][0]), to_tf32(sfrag[na][1]));
                *(float2*)&fsm[F_PS + (pr0 + 8) * FP_STRIDE + na * 8 + kc] =
                    make_float2(to_tf32(sfrag[na][2]), to_tf32(sfrag[na][3]));
            }
        }
        __syncwarp();

        // ---- O += P V : 8 ks(key) x 8 na(d) ----
#pragma unroll
        for (int ks = 0; ks < 8; ks++) {
            uint32_t af[4];
            LDMATRIX_X4(af, p_lm + ks * 32);
#pragma unroll
            for (int na = 0; na < 8; na++) {
                uint32_t bf[2];
                bf[0] = __float_as_uint(Vs[(ks * 8 + tig) * FV_STRIDE + na * 8 + g]);
                bf[1] = __float_as_uint(Vs[(ks * 8 + tig + 4) * FV_STRIDE + na * 8 + g]);
                MMA_TF32(o[na], af, bf);
            }
        }
        __syncthreads();          // all warps done with stage s -> reusable
    }

    // ---- epilogue: /l, tf32-round (A operand of out-proj), store ----
    const float i0 = 1.f / l0;
    const float i1 = 1.f / l1;
    const int r0 = q0 + wid * 16 + g;
    float* out0 = &g_attn[(size_t)(b * T_SEQ + r0) * D_MODEL + h * HEAD_DIM + 2 * tig];
    float* out1 = &g_attn[(size_t)(b * T_SEQ + r0 + 8) * D_MODEL + h * HEAD_DIM + 2 * tig];
#pragma unroll
    for (int na = 0; na < 8; na++) {
        *(float2*)&out0[na * 8] = make_float2(to_tf32(o[na][0] * i0), to_tf32(o[na][1] * i0));
        *(float2*)&out1[na * 8] = make_float2(to_tf32(o[na][2] * i1), to_tf32(o[na][3] * i1));
    }
}

// ---------------------------------------------------------------------------
// Launch
// ---------------------------------------------------------------------------
extern "C" void kernel_launch(void* const* d_in, const int* in_sizes, int n_in,
                              void* d_out, int out_size) {
    const float* x     = (const float*)d_in[0];   // [2,2048,1024]
    const float* w_qkv = (const float*)d_in[1];   // [1024,3072]
    const float* w_out = (const float*)d_in[2];   // [1024,1024]
    float* out = (float*)d_out;                   // [2,2048,1024]

    void *qkv_p, *attn_p, *xr_p, *wqkv_p, *wout_p;
    cudaGetSymbolAddress(&qkv_p,  g_qkv);
    cudaGetSymbolAddress(&attn_p, g_attn);
    cudaGetSymbolAddress(&xr_p,   g_xr);
    cudaGetSymbolAddress(&wqkv_p, g_wqkv_r);
    cudaGetSymbolAddress(&wout_p, g_wout_r);

    const int fa_smem = F_SMEM_FLOATS * (int)sizeof(float);    // 106496 B
    cudaFuncSetAttribute(flash_mma_kernel,
                         cudaFuncAttributeMaxDynamicSharedMemorySize, fa_smem);
    cudaFuncSetAttribute(gemm_mma<true>,
                         cudaFuncAttributeMaxDynamicSharedMemorySize, GS_SMEM_BYTES);
    cudaFuncSetAttribute(gemm_mma<false>,
                         cudaFuncAttributeMaxDynamicSharedMemorySize, GS_SMEM_BYTES);

    // 0) fused tf32 pre-round of all inputs
    round_all_kernel<<<(RN_TOTAL + 255) / 256, 256>>>(x, w_qkv, w_out);

    // 1) QKV projection (output tf32-rounded)
    gemm_mma<true><<<dim3(QKV_LD / 128, M_TOTAL / 128), 256, GS_SMEM_BYTES>>>(
        (const float*)xr_p, (const float*)wqkv_p, (float*)qkv_p,
        M_TOTAL, QKV_LD, D_MODEL);

    // 2) causal flash attention (tensor cores, R7 config)
    flash_mma_kernel<<<dim3(T_SEQ / 128, BATCH * N_HEADS), 256, fa_smem>>>();

    // 3) output projection
    gemm_mma<false><<<dim3(D_MODEL / 128, M_TOTAL / 128), 256, GS_SMEM_BYTES>>>(
        (const float*)attn_p, (const float*)wout_p, out,
        M_TOTAL, D_MODEL, D_MODEL);
}

// round 10
// speedup vs baseline: 1.0239x; 1.0093x over previous
#include <cuda_runtime.h>
#include <math.h>
#include <stdint.h>

// Problem constants
#define BATCH    2
#define T_SEQ    2048
#define D_MODEL  1024
#define N_HEADS  16
#define HEAD_DIM 64
#define M_TOTAL  (BATCH * T_SEQ)          // 4096 rows
#define QKV_LD   (3 * D_MODEL)            // 3072

// Scratch (allocation-free rule: __device__ globals)
__device__ float g_qkv   [M_TOTAL * QKV_LD];    // [4096, 3072] tf32-rounded (gemm<ROUND>)
__device__ float g_attn  [M_TOTAL * D_MODEL];   // [4096, 1024] tf32-rounded by flash
__device__ float g_xr    [M_TOTAL * D_MODEL];   // tf32-rounded x
__device__ float g_wqkv_r[D_MODEL * QKV_LD];    // tf32-rounded w_qkv
__device__ float g_wout_r[D_MODEL * D_MODEL];   // tf32-rounded w_out

__device__ __forceinline__ float to_tf32(float x) {
    float y;
    asm("cvt.rna.tf32.f32 %0, %1;" : "=f"(y) : "f"(x));
    return y;
}
__device__ __forceinline__ uint32_t smem_u32(const void* p) {
    uint32_t a;
    asm("{ .reg .u64 t; cvta.to.shared.u64 t, %1; cvt.u32.u64 %0, t; }" : "=r"(a) : "l"(p));
    return a;
}
__device__ __forceinline__ void cp16(uint32_t dst, const void* src) {
    asm volatile("cp.async.cg.shared.global [%0], [%1], 16;" :: "r"(dst), "l"(src) : "memory");
}
#define MMA_TF32(D, A, B) \
    asm volatile("mma.sync.aligned.m16n8k8.row.col.f32.tf32.tf32.f32 " \
                 "{%0,%1,%2,%3}, {%4,%5,%6,%7}, {%8,%9}, {%0,%1,%2,%3};" \
                 : "+f"((D)[0]), "+f"((D)[1]), "+f"((D)[2]), "+f"((D)[3]) \
                 : "r"((A)[0]), "r"((A)[1]), "r"((A)[2]), "r"((A)[3]), \
                   "r"((B)[0]), "r"((B)[1]))
#define LDMATRIX_X4(R, ADDR) \
    asm volatile("ldmatrix.sync.aligned.m8n8.x4.shared.b16 {%0,%1,%2,%3}, [%4];" \
                 : "=r"((R)[0]), "=r"((R)[1]), "=r"((R)[2]), "=r"((R)[3]) : "r"(ADDR))

// ---------------------------------------------------------------------------
// tf32 mma.sync GEMM (validated config; optional tf32 rounding of output).
// 128x128 block tile, 8 warps (2x4), warp tile 64x32, K-tile 32, 3-stage
// cp.async. A smem [128][36] (ldmatrix conflict-free), B [32][136] natural.
// ---------------------------------------------------------------------------
#define GS_A_FLOATS (128 * 36)
#define GS_B_FLOATS (32 * 136)
#define GS_STAGE    (GS_A_FLOATS + GS_B_FLOATS)   // 8960 floats
#define GS_SMEM_BYTES (3 * GS_STAGE * 4)          // 107520 B

__device__ __forceinline__ void issue_stage(uint32_t sb, const float* __restrict__ A,
                                            const float* __restrict__ B,
                                            int tid, int row0, int col0, int k0,
                                            int N, int K) {
#pragma unroll
    for (int i = 0; i < 4; i++) {
        int ff = tid + i * 256;
        int r  = ff >> 3, c4 = (ff & 7) * 4;
        cp16(sb + (r * 36 + c4) * 4, &A[(size_t)(row0 + r) * K + k0 + c4]);
        int k  = ff >> 5, n4 = (ff & 31) * 4;
        cp16(sb + (GS_A_FLOATS + k * 136 + n4) * 4, &B[(size_t)(k0 + k) * N + col0 + n4]);
    }
}

template <bool ROUND>
__global__ __launch_bounds__(256, 2) void gemm_mma(const float* __restrict__ A,
                                                   const float* __restrict__ B,
                                                   float* __restrict__ C,
                                                   int M, int N, int K) {
    extern __shared__ __align__(16) float gsm[];
    const uint32_t sb = smem_u32(gsm);
    const int tid  = threadIdx.x;
    const int lane = tid & 31;
    const int wid  = tid >> 5;
    const int wr = wid >> 2, wc = wid & 3;
    const int g  = lane >> 2, tig = lane & 3;
    const int row0 = blockIdx.y * 128;
    const int col0 = blockIdx.x * 128;

    float d[4][4][4] = {};
    const int T = K >> 5;

    issue_stage(sb + 0 * GS_STAGE * 4, A, B, tid, row0, col0, 0, N, K);
    asm volatile("cp.async.commit_group;" ::: "memory");
    issue_stage(sb + 1 * GS_STAGE * 4, A, B, tid, row0, col0, 32, N, K);
    asm volatile("cp.async.commit_group;" ::: "memory");

    const uint32_t a_base = sb + ((wr * 64 + ((lane >> 3) & 1) * 8 + (lane & 7)) * 36
                                  + ((lane >> 4) & 1) * 4) * 4;

    for (int t = 0; t < T; t++) {
        const int s = t % 3;
        asm volatile("cp.async.wait_group 1;" ::: "memory");
        __syncthreads();

        const uint32_t aS = a_base + s * GS_STAGE * 4;
        const uint32_t* sBu = (const uint32_t*)(gsm + s * GS_STAGE + GS_A_FLOATS);
        const int bcol = wc * 32 + g;

#pragma unroll
        for (int ks = 0; ks < 4; ks++) {
            uint32_t af[4][4], bf[4][2];
#pragma unroll
            for (int ma = 0; ma < 4; ma++)
                LDMATRIX_X4(af[ma], aS + ma * 2304 + ks * 32);
#pragma unroll
            for (int na = 0; na < 4; na++) {
                bf[na][0] = sBu[(ks * 8 + tig) * 136 + bcol + na * 8];
                bf[na][1] = sBu[(ks * 8 + tig + 4) * 136 + bcol + na * 8];
            }
#pragma unroll
            for (int ma = 0; ma < 4; ma++)
#pragma unroll
                for (int na = 0; na < 4; na++)
                    MMA_TF32(d[ma][na], af[ma], bf[na]);
        }

        if (t + 2 < T)
            issue_stage(sb + ((t + 2) % 3) * GS_STAGE * 4, A, B, tid,
                        row0, col0, (t + 2) * 32, N, K);
        asm volatile("cp.async.commit_group;" ::: "memory");
    }

#pragma unroll
    for (int ma = 0; ma < 4; ma++)
#pragma unroll
        for (int na = 0; na < 4; na++) {
            const int r = row0 + wr * 64 + ma * 16 + g;
            const int c = col0 + wc * 32 + na * 8 + tig * 2;
            float4 v = make_float4(d[ma][na][0], d[ma][na][1], d[ma][na][2], d[ma][na][3]);
            if (ROUND) {
                v.x = to_tf32(v.x); v.y = to_tf32(v.y);
                v.z = to_tf32(v.z); v.w = to_tf32(v.w);
            }
            *(float2*)&C[(size_t)r * N + c]       = make_float2(v.x, v.y);
            *(float2*)&C[(size_t)(r + 8) * N + c] = make_float2(v.z, v.w);
        }
}

// ---------------------------------------------------------------------------
// Fused tf32 pre-round: one kernel covers x, w_qkv, w_out
// ---------------------------------------------------------------------------
#define RN_X  (M_TOTAL * D_MODEL / 4)       // 1048576 float4
#define RN_WQ (D_MODEL * QKV_LD / 4)        //  786432
#define RN_WO (D_MODEL * D_MODEL / 4)       //  262144
#define RN_TOTAL (RN_X + RN_WQ + RN_WO)     // 2097152

__global__ void round_all_kernel(const float* __restrict__ x,
                                 const float* __restrict__ wq,
                                 const float* __restrict__ wo) {
    int i = blockIdx.x * blockDim.x + threadIdx.x;
    if (i >= RN_TOTAL) return;
    const float4* src;
    float4* dst;
    if (i < RN_X) {
        src = (const float4*)x + i;          dst = (float4*)g_xr + i;
    } else if (i < RN_X + RN_WQ) {
        src = (const float4*)wq + (i - RN_X); dst = (float4*)g_wqkv_r + (i - RN_X);
    } else {
        src = (const float4*)wo + (i - RN_X - RN_WQ);
        dst = (float4*)g_wout_r + (i - RN_X - RN_WQ);
    }
    float4 v = *src;
    v.x = to_tf32(v.x); v.y = to_tf32(v.y);
    v.z = to_tf32(v.z); v.w = to_tf32(v.w);
    *dst = v;
}

// ---------------------------------------------------------------------------
// Causal flash attention (tf32 mma.sync) — R7 config + R10 change:
// source-level 2-step-ahead rotating prefetch of B fragments in the S and
// PV MMA loops (3-slot buffer), double-buffered P ldmatrix in PV.
// ---------------------------------------------------------------------------
#define FK_STRIDE 68
#define FV_STRIDE 72
#define FP_STRIDE 68
#define F_STAGE_FLOATS (64 * FK_STRIDE + 64 * FV_STRIDE)   // 8960
#define F_PS (2 * F_STAGE_FLOATS)                          // 17920
#define F_SMEM_FLOATS (F_PS + 128 * FP_STRIDE)             // 26624 fl = 106496 B

__global__ __launch_bounds__(256, 2) void flash_mma_kernel() {
    extern __shared__ __align__(16) float fsm[];
    const uint32_t sb = smem_u32(fsm);
    const int tid  = threadIdx.x;
    const int lane = tid & 31;
    const int wid  = tid >> 5;
    const int g    = lane >> 2;
    const int tig  = lane & 3;

    const int qt = (gridDim.x - 1) - blockIdx.x;     // reversed: heavy first
    const int bh = blockIdx.y;
    const int b  = bh >> 4;
    const int h  = bh & 15;
    const int q0 = qt * 128;

    const float* base = g_qkv + (size_t)b * T_SEQ * QKV_LD + h * HEAD_DIM;
    const float* Qg = base;
    const float* Kg = base + D_MODEL;
    const float* Vg = base + 2 * D_MODEL;

    // ---- prologue: Q -> stage-0 region; KV(0) -> stage 1 ----
#pragma unroll
    for (int i = 0; i < 8; i++) {
        int ff = tid + i * 256;
        int r  = ff >> 4;
        int d4 = (ff & 15) * 4;
        cp16(sb + (r * FK_STRIDE + d4) * 4, &Qg[(size_t)(q0 + r) * QKV_LD + d4]);
    }
    asm volatile("cp.async.commit_group;" ::: "memory");
#pragma unroll
    for (int i = 0; i < 4; i++) {
        int ff = tid + i * 256;
        int r  = ff >> 4;
        int d4 = (ff & 15) * 4;
        const size_t grow = (size_t)r * QKV_LD + d4;
        cp16(sb + (F_STAGE_FLOATS + r * FK_STRIDE + d4) * 4, &Kg[grow]);
        cp16(sb + (F_STAGE_FLOATS + 64 * FK_STRIDE + r * FV_STRIDE + d4) * 4, &Vg[grow]);
    }
    asm volatile("cp.async.commit_group;" ::: "memory");
    asm volatile("cp.async.wait_group 1;" ::: "memory");   // Q complete
    __syncthreads();

    // ---- extract Q fragments once (loop-invariant) ----
    const int lm_row = wid * 16 + ((lane >> 3) & 1) * 8 + (lane & 7);
    const int lm_col = ((lane >> 4) & 1) * 4;
    uint32_t qf[8][4];
    {
        const uint32_t q_lm = sb + (lm_row * FK_STRIDE + lm_col) * 4;
#pragma unroll
        for (int ks = 0; ks < 8; ks++)
            LDMATRIX_X4(qf[ks], q_lm + ks * 32);
    }
    __syncthreads();              // Q region (stage 0) now free for KV(1)

    const uint32_t p_lm = sb + (F_PS + lm_row * FP_STRIDE + lm_col) * 4;

    const float NEG_INF = __int_as_float(0xff800000u);
    const float scale = 0.125f;
    float o[8][4] = {};
    float m0 = NEG_INF, m1 = NEG_INF, l0 = 0.f, l1 = 0.f;

    const int nkt = 2 * qt + 2;
    for (int kt = 0; kt < nkt; kt++) {
        const int s = (kt + 1) & 1;          // stage holding KV(kt)

        if (kt + 1 < nkt) {
            const int sd = kt & 1;
#pragma unroll
            for (int i = 0; i < 4; i++) {
                int ff = tid + i * 256;
                int r  = ff >> 4;
                int d4 = (ff & 15) * 4;
                const size_t grow = (size_t)((kt + 1) * 64 + r) * QKV_LD + d4;
                cp16(sb + (sd * F_STAGE_FLOATS + r * FK_STRIDE + d4) * 4, &Kg[grow]);
                cp16(sb + (sd * F_STAGE_FLOATS + 64 * FK_STRIDE + r * FV_STRIDE + d4) * 4,
                     &Vg[grow]);
            }
            asm volatile("cp.async.commit_group;" ::: "memory");
            asm volatile("cp.async.wait_group 1;" ::: "memory");   // KV(kt) ready
        } else {
            asm volatile("cp.async.wait_group 0;" ::: "memory");
        }
        __syncthreads();                      // KV(kt) visible to all warps

        const float* Ks = fsm + s * F_STAGE_FLOATS;
        const float* Vs = Ks + 64 * FK_STRIDE;

        // ---- S = Q K^T : linearized 64 steps, 3-slot B prefetch 2 ahead ----
        float sfrag[8][4] = {};
        uint32_t bfb[3][2];
        bfb[0][0] = __float_as_uint(Ks[g * FK_STRIDE + tig]);
        bfb[0][1] = __float_as_uint(Ks[g * FK_STRIDE + tig + 4]);
        bfb[1][0] = __float_as_uint(Ks[(8 + g) * FK_STRIDE + tig]);
        bfb[1][1] = __float_as_uint(Ks[(8 + g) * FK_STRIDE + tig + 4]);
#pragma unroll
        for (int ks = 0; ks < 8; ks++) {
#pragma unroll
            for (int na = 0; na < 8; na++) {
                const int idx = ks * 8 + na;
                const int cur = idx % 3;
                if (idx + 2 < 64) {
                    const int nk = (idx + 2) >> 3, nn = (idx + 2) & 7;
                    bfb[(cur + 2) % 3][0] =
                        __float_as_uint(Ks[(nn * 8 + g) * FK_STRIDE + nk * 8 + tig]);
                    bfb[(cur + 2) % 3][1] =
                        __float_as_uint(Ks[(nn * 8 + g) * FK_STRIDE + nk * 8 + tig + 4]);
                }
                MMA_TF32(sfrag[na], qf[ks], bfb[cur]);
            }
        }

        // ---- scale + causal mask ----
        const bool diag = (kt >= 2 * qt);
        const int qr0 = q0 + wid * 16 + g;
        const int qr1 = qr0 + 8;
#pragma unroll
        for (int na = 0; na < 8; na++) {
            const int kg = kt * 64 + na * 8 + 2 * tig;
            sfrag[na][0] *= scale; sfrag[na][1] *= scale;
            sfrag[na][2] *= scale; sfrag[na][3] *= scale;
            if (diag) {
                if (kg     > qr0) sfrag[na][0] = NEG_INF;
                if (kg + 1 > qr0) sfrag[na][1] = NEG_INF;
                if (kg     > qr1) sfrag[na][2] = NEG_INF;
                if (kg + 1 > qr1) sfrag[na][3] = NEG_INF;
            }
        }

        // ---- online softmax (rows g / g+8; reduce across quad tig) ----
        float mx0 = NEG_INF, mx1 = NEG_INF;
#pragma unroll
        for (int na = 0; na < 8; na++) {
            mx0 = fmaxf(mx0, fmaxf(sfrag[na][0], sfrag[na][1]));
            mx1 = fmaxf(mx1, fmaxf(sfrag[na][2], sfrag[na][3]));
        }
        mx0 = fmaxf(mx0, __shfl_xor_sync(0xffffffffu, mx0, 1));
        mx0 = fmaxf(mx0, __shfl_xor_sync(0xffffffffu, mx0, 2));
        mx1 = fmaxf(mx1, __shfl_xor_sync(0xffffffffu, mx1, 1));
        mx1 = fmaxf(mx1, __shfl_xor_sync(0xffffffffu, mx1, 2));
        const float mn0 = fmaxf(m0, mx0);
        const float mn1 = fmaxf(m1, mx1);
        const float a0 = __expf(m0 - mn0);
        const float a1 = __expf(m1 - mn1);
        float sum0 = 0.f, sum1 = 0.f;
#pragma unroll
        for (int na = 0; na < 8; na++) {
            sfrag[na][0] = __expf(sfrag[na][0] - mn0);
            sfrag[na][1] = __expf(sfrag[na][1] - mn0);
            sfrag[na][2] = __expf(sfrag[na][2] - mn1);
            sfrag[na][3] = __expf(sfrag[na][3] - mn1);
            sum0 += sfrag[na][0] + sfrag[na][1];
            sum1 += sfrag[na][2] + sfrag[na][3];
        }
        sum0 += __shfl_xor_sync(0xffffffffu, sum0, 1);
        sum0 += __shfl_xor_sync(0xffffffffu, sum0, 2);
        sum1 += __shfl_xor_sync(0xffffffffu, sum1, 1);
        sum1 += __shfl_xor_sync(0xffffffffu, sum1, 2);
        l0 = l0 * a0 + sum0;  m0 = mn0;
        l1 = l1 * a1 + sum1;  m1 = mn1;
#pragma unroll
        for (int na = 0; na < 8; na++) {
            o[na][0] *= a0; o[na][1] *= a0;
            o[na][2] *= a1; o[na][3] *= a1;
        }

        // ---- P (tf32) -> warp-private smem rows; __syncwarp suffices ----
        {
            const int pr0 = wid * 16 + g;
            const int kc  = 2 * tig;
#pragma unroll
            for (int na = 0; na < 8; na++) {
                *(float2*)&fsm[F_PS + pr0 * FP_STRIDE + na * 8 + kc] =
                    make_float2(to_tf32(sfrag[na][0]), to_tf32(sfrag[na][1]));
                *(float2*)&fsm[F_PS + (pr0 + 8) * FP_STRIDE + na * 8 + kc] =
                    make_float2(to_tf32(sfrag[na][2]), to_tf32(sfrag[na][3]));
            }
        }
        __syncwarp();

        // ---- O += P V : linearized, double-buffered P + 3-slot V prefetch ----
        {
            uint32_t afb[2][4];
            LDMATRIX_X4(afb[0], p_lm);
            uint32_t vfb[3][2];
            vfb[0][0] = __float_as_uint(Vs[tig * FV_STRIDE + g]);
            vfb[0][1] = __float_as_uint(Vs[(tig + 4) * FV_STRIDE + g]);
            vfb[1][0] = __float_as_uint(Vs[tig * FV_STRIDE + 8 + g]);
            vfb[1][1] = __float_as_uint(Vs[(tig + 4) * FV_STRIDE + 8 + g]);
#pragma unroll
            for (int ks = 0; ks < 8; ks++) {
                if (ks < 7) LDMATRIX_X4(afb[(ks + 1) & 1], p_lm + (ks + 1) * 32);
#pragma unroll
                for (int na = 0; na < 8; na++) {
                    const int idx = ks * 8 + na;
                    const int cur = idx % 3;
                    if (idx + 2 < 64) {
                        const int nk = (idx + 2) >> 3, nn = (idx + 2) & 7;
                        vfb[(cur + 2) % 3][0] =
                            __float_as_uint(Vs[(nk * 8 + tig) * FV_STRIDE + nn * 8 + g]);
                        vfb[(cur + 2) % 3][1] =
                            __float_as_uint(Vs[(nk * 8 + tig + 4) * FV_STRIDE + nn * 8 + g]);
                    }
                    MMA_TF32(o[na], afb[ks & 1], vfb[cur]);
                }
            }
        }
        __syncthreads();          // all warps done with stage s -> reusable
    }

    // ---- epilogue: /l, tf32-round (A operand of out-proj), store ----
    const float i0 = 1.f / l0;
    const float i1 = 1.f / l1;
    const int r0 = q0 + wid * 16 + g;
    float* out0 = &g_attn[(size_t)(b * T_SEQ + r0) * D_MODEL + h * HEAD_DIM + 2 * tig];
    float* out1 = &g_attn[(size_t)(b * T_SEQ + r0 + 8) * D_MODEL + h * HEAD_DIM + 2 * tig];
#pragma unroll
    for (int na = 0; na < 8; na++) {
        *(float2*)&out0[na * 8] = make_float2(to_tf32(o[na][0] * i0), to_tf32(o[na][1] * i0));
        *(float2*)&out1[na * 8] = make_float2(to_tf32(o[na][2] * i1), to_tf32(o[na][3] * i1));
    }
}

// ---------------------------------------------------------------------------
// Launch
// ---------------------------------------------------------------------------
extern "C" void kernel_launch(void* const* d_in, const int* in_sizes, int n_in,
                              void* d_out, int out_size) {
    const float* x     = (const float*)d_in[0];   // [2,2048,1024]
    const float* w_qkv = (const float*)d_in[1];   // [1024,3072]
    const float* w_out = (const float*)d_in[2];   // [1024,1024]
    float* out = (float*)d_out;                   // [2,2048,1024]

    void *qkv_p, *attn_p, *xr_p, *wqkv_p, *wout_p;
    cudaGetSymbolAddress(&qkv_p,  g_qkv);
    cudaGetSymbolAddress(&attn_p, g_attn);
    cudaGetSymbolAddress(&xr_p,   g_xr);
    cudaGetSymbolAddress(&wqkv_p, g_wqkv_r);
    cudaGetSymbolAddress(&wout_p, g_wout_r);

    const int fa_smem = F_SMEM_FLOATS * (int)sizeof(float);    // 106496 B
    cudaFuncSetAttribute(flash_mma_kernel,
                         cudaFuncAttributeMaxDynamicSharedMemorySize, fa_smem);
    cudaFuncSetAttribute(gemm_mma<true>,
                         cudaFuncAttributeMaxDynamicSharedMemorySize, GS_SMEM_BYTES);
    cudaFuncSetAttribute(gemm_mma<false>,
                         cudaFuncAttributeMaxDynamicSharedMemorySize, GS_SMEM_BYTES);

    // 0) fused tf32 pre-round of all inputs
    round_all_kernel<<<(RN_TOTAL + 255) / 256, 256>>>(x, w_qkv, w_out);

    // 1) QKV projection (output tf32-rounded)
    gemm_mma<true><<<dim3(QKV_LD / 128, M_TOTAL / 128), 256, GS_SMEM_BYTES>>>(
        (const float*)xr_p, (const float*)wqkv_p, (float*)qkv_p,
        M_TOTAL, QKV_LD, D_MODEL);

    // 2) causal flash attention (tensor cores, prefetch-pipelined MMA loops)
    flash_mma_kernel<<<dim3(T_SEQ / 128, BATCH * N_HEADS), 256, fa_smem>>>();

    // 3) output projection
    gemm_mma<false><<<dim3(D_MODEL / 128, M_TOTAL / 128), 256, GS_SMEM_BYTES>>>(
        (const float*)attn_p, (const float*)wout_p, out,
        M_TOTAL, D_MODEL, D_MODEL);
}

// round 11
// speedup vs baseline: 1.0824x; 1.0571x over previous
#include <cuda_runtime.h>
#include <math.h>
#include <stdint.h>

// Problem constants
#define BATCH    2
#define T_SEQ    2048
#define D_MODEL  1024
#define N_HEADS  16
#define HEAD_DIM 64
#define M_TOTAL  (BATCH * T_SEQ)          // 4096 rows
#define QKV_LD   (3 * D_MODEL)            // 3072

// Scratch (allocation-free rule: __device__ globals)
__device__ float g_qkv   [M_TOTAL * QKV_LD];    // [4096, 3072] tf32-rounded (gemm<ROUND>)
__device__ float g_attn  [M_TOTAL * D_MODEL];   // [4096, 1024] tf32-rounded by flash
__device__ float g_xr    [M_TOTAL * D_MODEL];   // tf32-rounded x
__device__ float g_wqkv_r[D_MODEL * QKV_LD];    // tf32-rounded w_qkv
__device__ float g_wout_r[D_MODEL * D_MODEL];   // tf32-rounded w_out

__device__ __forceinline__ float to_tf32(float x) {
    float y;
    asm("cvt.rna.tf32.f32 %0, %1;" : "=f"(y) : "f"(x));
    return y;
}
__device__ __forceinline__ uint32_t smem_u32(const void* p) {
    uint32_t a;
    asm("{ .reg .u64 t; cvta.to.shared.u64 t, %1; cvt.u32.u64 %0, t; }" : "=r"(a) : "l"(p));
    return a;
}
__device__ __forceinline__ void cp16(uint32_t dst, const void* src) {
    asm volatile("cp.async.cg.shared.global [%0], [%1], 16;" :: "r"(dst), "l"(src) : "memory");
}
#define MMA_TF32(D, A, B) \
    asm volatile("mma.sync.aligned.m16n8k8.row.col.f32.tf32.tf32.f32 " \
                 "{%0,%1,%2,%3}, {%4,%5,%6,%7}, {%8,%9}, {%0,%1,%2,%3};" \
                 : "+f"((D)[0]), "+f"((D)[1]), "+f"((D)[2]), "+f"((D)[3]) \
                 : "r"((A)[0]), "r"((A)[1]), "r"((A)[2]), "r"((A)[3]), \
                   "r"((B)[0]), "r"((B)[1]))
#define LDMATRIX_X4(R, ADDR) \
    asm volatile("ldmatrix.sync.aligned.m8n8.x4.shared.b16 {%0,%1,%2,%3}, [%4];" \
                 : "=r"((R)[0]), "=r"((R)[1]), "=r"((R)[2]), "=r"((R)[3]) : "r"(ADDR))

// ---------------------------------------------------------------------------
// tf32 mma.sync GEMM (validated config; optional tf32 rounding of output).
// ---------------------------------------------------------------------------
#define GS_A_FLOATS (128 * 36)
#define GS_B_FLOATS (32 * 136)
#define GS_STAGE    (GS_A_FLOATS + GS_B_FLOATS)   // 8960 floats
#define GS_SMEM_BYTES (3 * GS_STAGE * 4)          // 107520 B

__device__ __forceinline__ void issue_stage(uint32_t sb, const float* __restrict__ A,
                                            const float* __restrict__ B,
                                            int tid, int row0, int col0, int k0,
                                            int N, int K) {
#pragma unroll
    for (int i = 0; i < 4; i++) {
        int ff = tid + i * 256;
        int r  = ff >> 3, c4 = (ff & 7) * 4;
        cp16(sb + (r * 36 + c4) * 4, &A[(size_t)(row0 + r) * K + k0 + c4]);
        int k  = ff >> 5, n4 = (ff & 31) * 4;
        cp16(sb + (GS_A_FLOATS + k * 136 + n4) * 4, &B[(size_t)(k0 + k) * N + col0 + n4]);
    }
}

template <bool ROUND>
__global__ __launch_bounds__(256, 2) void gemm_mma(const float* __restrict__ A,
                                                   const float* __restrict__ B,
                                                   float* __restrict__ C,
                                                   int M, int N, int K) {
    extern __shared__ __align__(16) float gsm[];
    const uint32_t sb = smem_u32(gsm);
    const int tid  = threadIdx.x;
    const int lane = tid & 31;
    const int wid  = tid >> 5;
    const int wr = wid >> 2, wc = wid & 3;
    const int g  = lane >> 2, tig = lane & 3;
    const int row0 = blockIdx.y * 128;
    const int col0 = blockIdx.x * 128;

    float d[4][4][4] = {};
    const int T = K >> 5;

    issue_stage(sb + 0 * GS_STAGE * 4, A, B, tid, row0, col0, 0, N, K);
    asm volatile("cp.async.commit_group;" ::: "memory");
    issue_stage(sb + 1 * GS_STAGE * 4, A, B, tid, row0, col0, 32, N, K);
    asm volatile("cp.async.commit_group;" ::: "memory");

    const uint32_t a_base = sb + ((wr * 64 + ((lane >> 3) & 1) * 8 + (lane & 7)) * 36
                                  + ((lane >> 4) & 1) * 4) * 4;

    for (int t = 0; t < T; t++) {
        const int s = t % 3;
        asm volatile("cp.async.wait_group 1;" ::: "memory");
        __syncthreads();

        const uint32_t aS = a_base + s * GS_STAGE * 4;
        const uint32_t* sBu = (const uint32_t*)(gsm + s * GS_STAGE + GS_A_FLOATS);
        const int bcol = wc * 32 + g;

#pragma unroll
        for (int ks = 0; ks < 4; ks++) {
            uint32_t af[4][4], bf[4][2];
#pragma unroll
            for (int ma = 0; ma < 4; ma++)
                LDMATRIX_X4(af[ma], aS + ma * 2304 + ks * 32);
#pragma unroll
            for (int na = 0; na < 4; na++) {
                bf[na][0] = sBu[(ks * 8 + tig) * 136 + bcol + na * 8];
                bf[na][1] = sBu[(ks * 8 + tig + 4) * 136 + bcol + na * 8];
            }
#pragma unroll
            for (int ma = 0; ma < 4; ma++)
#pragma unroll
                for (int na = 0; na < 4; na++)
                    MMA_TF32(d[ma][na], af[ma], bf[na]);
        }

        if (t + 2 < T)
            issue_stage(sb + ((t + 2) % 3) * GS_STAGE * 4, A, B, tid,
                        row0, col0, (t + 2) * 32, N, K);
        asm volatile("cp.async.commit_group;" ::: "memory");
    }

#pragma unroll
    for (int ma = 0; ma < 4; ma++)
#pragma unroll
        for (int na = 0; na < 4; na++) {
            const int r = row0 + wr * 64 + ma * 16 + g;
            const int c = col0 + wc * 32 + na * 8 + tig * 2;
            float4 v = make_float4(d[ma][na][0], d[ma][na][1], d[ma][na][2], d[ma][na][3]);
            if (ROUND) {
                v.x = to_tf32(v.x); v.y = to_tf32(v.y);
                v.z = to_tf32(v.z); v.w = to_tf32(v.w);
            }
            *(float2*)&C[(size_t)r * N + c]       = make_float2(v.x, v.y);
            *(float2*)&C[(size_t)(r + 8) * N + c] = make_float2(v.z, v.w);
        }
}

// ---------------------------------------------------------------------------
// Fused tf32 pre-round: one kernel covers x, w_qkv, w_out
// ---------------------------------------------------------------------------
#define RN_X  (M_TOTAL * D_MODEL / 4)       // 1048576 float4
#define RN_WQ (D_MODEL * QKV_LD / 4)        //  786432
#define RN_WO (D_MODEL * D_MODEL / 4)       //  262144
#define RN_TOTAL (RN_X + RN_WQ + RN_WO)     // 2097152

__global__ void round_all_kernel(const float* __restrict__ x,
                                 const float* __restrict__ wq,
                                 const float* __restrict__ wo) {
    int i = blockIdx.x * blockDim.x + threadIdx.x;
    if (i >= RN_TOTAL) return;
    const float4* src;
    float4* dst;
    if (i < RN_X) {
        src = (const float4*)x + i;          dst = (float4*)g_xr + i;
    } else if (i < RN_X + RN_WQ) {
        src = (const float4*)wq + (i - RN_X); dst = (float4*)g_wqkv_r + (i - RN_X);
    } else {
        src = (const float4*)wo + (i - RN_X - RN_WQ);
        dst = (float4*)g_wout_r + (i - RN_X - RN_WQ);
    }
    float4 v = *src;
    v.x = to_tf32(v.x); v.y = to_tf32(v.y);
    v.z = to_tf32(v.z); v.w = to_tf32(v.w);
    *dst = v;
}

// ---------------------------------------------------------------------------
// Causal flash attention (tf32 mma.sync) — R11: 4 CTAs/SM for phase overlap.
// q-tile 64, key-tile 32, 128 threads (4 warps, warp = 16 q rows).
// Q fragments hoisted once (Q staged in KV stage-0 region), double-buffered
// KV cp.async stages, warp-private P rows (__syncwarp).
// smem/CTA ~44 KB, regs ~112 -> 4 independent CTAs per SM: while one CTA
// runs its serial softmax chain, others issue HMMA.
// ---------------------------------------------------------------------------
#define FK_STRIDE 68
#define FV_STRIDE 72
#define FP_STRIDE 36                                        // 32 keys + 4 pad
#define F_STAGE_FLOATS (32 * FK_STRIDE + 32 * FV_STRIDE)    // 4480
#define F_PS (2 * F_STAGE_FLOATS)                           // 8960
#define F_SMEM_FLOATS (F_PS + 64 * FP_STRIDE)               // 11264 fl = 45056 B

__global__ __launch_bounds__(128, 4) void flash_mma_kernel() {
    extern __shared__ __align__(16) float fsm[];
    const uint32_t sb = smem_u32(fsm);
    const int tid  = threadIdx.x;
    const int lane = tid & 31;
    const int wid  = tid >> 5;        // 0..3, warp owns q rows [16wid,16wid+16)
    const int g    = lane >> 2;
    const int tig  = lane & 3;

    const int qt = (gridDim.x - 1) - blockIdx.x;     // reversed: heavy first
    const int bh = blockIdx.y;
    const int b  = bh >> 4;
    const int h  = bh & 15;
    const int q0 = qt * 64;

    const float* base = g_qkv + (size_t)b * T_SEQ * QKV_LD + h * HEAD_DIM;
    const float* Qg = base;
    const float* Kg = base + D_MODEL;
    const float* Vg = base + 2 * D_MODEL;

    // ---- prologue: Q (64x64) -> stage-0 region; KV(0) -> stage 1 ----
#pragma unroll
    for (int i = 0; i < 8; i++) {
        int ff = tid + i * 128;       // 0..1023 float4
        int r  = ff >> 4;             // q row 0..63
        int d4 = (ff & 15) * 4;
        cp16(sb + (r * FK_STRIDE + d4) * 4, &Qg[(size_t)(q0 + r) * QKV_LD + d4]);
    }
    asm volatile("cp.async.commit_group;" ::: "memory");
#pragma unroll
    for (int i = 0; i < 4; i++) {
        int ff = tid + i * 128;       // 0..511
        int r  = ff >> 4;             // key row 0..31
        int d4 = (ff & 15) * 4;
        const size_t grow = (size_t)r * QKV_LD + d4;
        cp16(sb + (F_STAGE_FLOATS + r * FK_STRIDE + d4) * 4, &Kg[grow]);
        cp16(sb + (F_STAGE_FLOATS + 32 * FK_STRIDE + r * FV_STRIDE + d4) * 4, &Vg[grow]);
    }
    asm volatile("cp.async.commit_group;" ::: "memory");
    asm volatile("cp.async.wait_group 1;" ::: "memory");   // Q complete
    __syncthreads();

    // ---- extract Q fragments once (Q lives in stage-0 region; stride 68) ----
    const int lm_rr  = ((lane >> 3) & 1) * 8 + (lane & 7);
    const int lm_col = ((lane >> 4) & 1) * 4;
    uint32_t qf[8][4];
    {
        const uint32_t q_lm = sb + ((wid * 16 + lm_rr) * FK_STRIDE + lm_col) * 4;
#pragma unroll
        for (int ks = 0; ks < 8; ks++)
            LDMATRIX_X4(qf[ks], q_lm + ks * 32);
    }
    __syncthreads();              // Q region (stage 0) now free for KV(1)

    const uint32_t p_lm = sb + (F_PS + (wid * 16 + lm_rr) * FP_STRIDE + lm_col) * 4;

    const float NEG_INF = __int_as_float(0xff800000u);
    const float scale = 0.125f;
    float o[8][4] = {};
    float m0 = NEG_INF, m1 = NEG_INF, l0 = 0.f, l1 = 0.f;

    const int nkt = 2 * qt + 2;                       // 32-key tiles
    for (int kt = 0; kt < nkt; kt++) {
        const int s = (kt + 1) & 1;                   // stage holding KV(kt)

        if (kt + 1 < nkt) {
            const int sd = kt & 1;
#pragma unroll
            for (int i = 0; i < 4; i++) {
                int ff = tid + i * 128;
                int r  = ff >> 4;
                int d4 = (ff & 15) * 4;
                const size_t grow = (size_t)((kt + 1) * 32 + r) * QKV_LD + d4;
                cp16(sb + (sd * F_STAGE_FLOATS + r * FK_STRIDE + d4) * 4, &Kg[grow]);
                cp16(sb + (sd * F_STAGE_FLOATS + 32 * FK_STRIDE + r * FV_STRIDE + d4) * 4,
                     &Vg[grow]);
            }
            asm volatile("cp.async.commit_group;" ::: "memory");
            asm volatile("cp.async.wait_group 1;" ::: "memory");   // KV(kt) ready
        } else {
            asm volatile("cp.async.wait_group 0;" ::: "memory");
        }
        __syncthreads();                      // KV(kt) visible to all warps

        const float* Ks = fsm + s * F_STAGE_FLOATS;
        const float* Vs = Ks + 32 * FK_STRIDE;

        // ---- S = Q K^T : 8 ks x 4 na (32 keys) ----
        float sfrag[4][4] = {};
#pragma unroll
        for (int ks = 0; ks < 8; ks++) {
#pragma unroll
            for (int na = 0; na < 4; na++) {
                uint32_t bf[2];
                bf[0] = __float_as_uint(Ks[(na * 8 + g) * FK_STRIDE + ks * 8 + tig]);
                bf[1] = __float_as_uint(Ks[(na * 8 + g) * FK_STRIDE + ks * 8 + tig + 4]);
                MMA_TF32(sfrag[na], qf[ks], bf);
            }
        }

        // ---- scale + causal mask ----
        const bool diag = (kt >= 2 * qt);
        const int qr0 = q0 + wid * 16 + g;
        const int qr1 = qr0 + 8;
#pragma unroll
        for (int na = 0; na < 4; na++) {
            const int kg = kt * 32 + na * 8 + 2 * tig;
            sfrag[na][0] *= scale; sfrag[na][1] *= scale;
            sfrag[na][2] *= scale; sfrag[na][3] *= scale;
            if (diag) {
                if (kg     > qr0) sfrag[na][0] = NEG_INF;
                if (kg + 1 > qr0) sfrag[na][1] = NEG_INF;
                if (kg     > qr1) sfrag[na][2] = NEG_INF;
                if (kg + 1 > qr1) sfrag[na][3] = NEG_INF;
            }
        }

        // ---- online softmax (rows g / g+8; reduce across quad tig) ----
        float mx0 = NEG_INF, mx1 = NEG_INF;
#pragma unroll
        for (int na = 0; na < 4; na++) {
            mx0 = fmaxf(mx0, fmaxf(sfrag[na][0], sfrag[na][1]));
            mx1 = fmaxf(mx1, fmaxf(sfrag[na][2], sfrag[na][3]));
        }
        mx0 = fmaxf(mx0, __shfl_xor_sync(0xffffffffu, mx0, 1));
        mx0 = fmaxf(mx0, __shfl_xor_sync(0xffffffffu, mx0, 2));
        mx1 = fmaxf(mx1, __shfl_xor_sync(0xffffffffu, mx1, 1));
        mx1 = fmaxf(mx1, __shfl_xor_sync(0xffffffffu, mx1, 2));
        const float mn0 = fmaxf(m0, mx0);
        const float mn1 = fmaxf(m1, mx1);
        const float a0 = __expf(m0 - mn0);
        const float a1 = __expf(m1 - mn1);
        float sum0 = 0.f, sum1 = 0.f;
#pragma unroll
        for (int na = 0; na < 4; na++) {
            sfrag[na][0] = __expf(sfrag[na][0] - mn0);
            sfrag[na][1] = __expf(sfrag[na][1] - mn0);
            sfrag[na][2] = __expf(sfrag[na][2] - mn1);
            sfrag[na][3] = __expf(sfrag[na][3] - mn1);
            sum0 += sfrag[na][0] + sfrag[na][1];
            sum1 += sfrag[na][2] + sfrag[na][3];
        }
        sum0 += __shfl_xor_sync(0xffffffffu, sum0, 1);
        sum0 += __shfl_xor_sync(0xffffffffu, sum0, 2);
        sum1 += __shfl_xor_sync(0xffffffffu, sum1, 1);
        sum1 += __shfl_xor_sync(0xffffffffu, sum1, 2);
        l0 = l0 * a0 + sum0;  m0 = mn0;
        l1 = l1 * a1 + sum1;  m1 = mn1;
#pragma unroll
        for (int na = 0; na < 8; na++) {
            o[na][0] *= a0; o[na][1] *= a0;
            o[na][2] *= a1; o[na][3] *= a1;
        }

        // ---- P (tf32) -> warp-private smem rows; __syncwarp suffices ----
        {
            const int pr0 = wid * 16 + g;
            const int kc  = 2 * tig;
#pragma unroll
            for (int na = 0; na < 4; na++) {
                *(float2*)&fsm[F_PS + pr0 * FP_STRIDE + na * 8 + kc] =
                    make_float2(to_tf32(sfrag[na][0]), to_tf32(sfrag[na][1]));
                *(float2*)&fsm[F_PS + (pr0 + 8) * FP_STRIDE + na * 8 + kc] =
                    make_float2(to_tf32(sfrag[na][2]), to_tf32(sfrag[na][3]));
            }
        }
        __syncwarp();

        // ---- O += P V : 4 ks (32 keys) x 8 na (64 d) ----
#pragma unroll
        for (int ks = 0; ks < 4; ks++) {
            uint32_t af[4];
            LDMATRIX_X4(af, p_lm + ks * 32);
#pragma unroll
            for (int na = 0; na < 8; na++) {
                uint32_t bf[2];
                bf[0] = __float_as_uint(Vs[(ks * 8 + tig) * FV_STRIDE + na * 8 + g]);
                bf[1] = __float_as_uint(Vs[(ks * 8 + tig + 4) * FV_STRIDE + na * 8 + g]);
                MMA_TF32(o[na], af, bf);
            }
        }
        __syncthreads();          // all warps done with stage s -> reusable
    }

    // ---- epilogue: /l, tf32-round (A operand of out-proj), store ----
    const float i0 = 1.f / l0;
    const float i1 = 1.f / l1;
    const int r0 = q0 + wid * 16 + g;
    float* out0 = &g_attn[(size_t)(b * T_SEQ + r0) * D_MODEL + h * HEAD_DIM + 2 * tig];
    float* out1 = &g_attn[(size_t)(b * T_SEQ + r0 + 8) * D_MODEL + h * HEAD_DIM + 2 * tig];
#pragma unroll
    for (int na = 0; na < 8; na++) {
        *(float2*)&out0[na * 8] = make_float2(to_tf32(o[na][0] * i0), to_tf32(o[na][1] * i0));
        *(float2*)&out1[na * 8] = make_float2(to_tf32(o[na][2] * i1), to_tf32(o[na][3] * i1));
    }
}

// ---------------------------------------------------------------------------
// Launch
// ---------------------------------------------------------------------------
extern "C" void kernel_launch(void* const* d_in, const int* in_sizes, int n_in,
                              void* d_out, int out_size) {
    const float* x     = (const float*)d_in[0];   // [2,2048,1024]
    const float* w_qkv = (const float*)d_in[1];   // [1024,3072]
    const float* w_out = (const float*)d_in[2];   // [1024,1024]
    float* out = (float*)d_out;                   // [2,2048,1024]

    void *qkv_p, *attn_p, *xr_p, *wqkv_p, *wout_p;
    cudaGetSymbolAddress(&qkv_p,  g_qkv);
    cudaGetSymbolAddress(&attn_p, g_attn);
    cudaGetSymbolAddress(&xr_p,   g_xr);
    cudaGetSymbolAddress(&wqkv_p, g_wqkv_r);
    cudaGetSymbolAddress(&wout_p, g_wout_r);

    const int fa_smem = F_SMEM_FLOATS * (int)sizeof(float);    // 45056 B
    cudaFuncSetAttribute(flash_mma_kernel,
                         cudaFuncAttributeMaxDynamicSharedMemorySize, fa_smem);
    cudaFuncSetAttribute(gemm_mma<true>,
                         cudaFuncAttributeMaxDynamicSharedMemorySize, GS_SMEM_BYTES);
    cudaFuncSetAttribute(gemm_mma<false>,
                         cudaFuncAttributeMaxDynamicSharedMemorySize, GS_SMEM_BYTES);

    // 0) fused tf32 pre-round of all inputs
    round_all_kernel<<<(RN_TOTAL + 255) / 256, 256>>>(x, w_qkv, w_out);

    // 1) QKV projection (output tf32-rounded)
    gemm_mma<true><<<dim3(QKV_LD / 128, M_TOTAL / 128), 256, GS_SMEM_BYTES>>>(
        (const float*)xr_p, (const float*)wqkv_p, (float*)qkv_p,
        M_TOTAL, QKV_LD, D_MODEL);

    // 2) causal flash attention (4 CTAs/SM, 64-q tiles, 32-key tiles)
    flash_mma_kernel<<<dim3(T_SEQ / 64, BATCH * N_HEADS), 128, fa_smem>>>();

    // 3) output projection
    gemm_mma<false><<<dim3(D_MODEL / 128, M_TOTAL / 128), 256, GS_SMEM_BYTES>>>(
        (const float*)attn_p, (const float*)wout_p, out,
        M_TOTAL, D_MODEL, D_MODEL);
}